// round 11
// baseline (speedup 1.0000x reference)
#include <cuda_runtime.h>
#include <cuda_bf16.h>
#include <cstdint>

// out layout (fp32): [0,BS) imputed | [BS,2BS) disc | [2BS,3BS) latent | [3BS,4BS) recon
// BS = B*16

#define S16 16

__device__ float g_dec_recon[16];        // batch-independent decoder output
__device__ float g_h[2][32768 * 16];     // per-direction final hidden states

// ---- activations ----------------------------------------------------------
__device__ __forceinline__ float fast_ex2(float x) {
    float y; asm("ex2.approx.f32 %0, %1;" : "=f"(y) : "f"(x)); return y;
}
__device__ __forceinline__ float fast_rcp(float x) {
    float y; asm("rcp.approx.f32 %0, %1;" : "=f"(y) : "f"(x)); return y;
}
__device__ __forceinline__ float sigmoidf_(float x) {
    return fast_rcp(1.0f + fast_ex2(-1.4426950408889634f * x));
}
__device__ __forceinline__ float tanhf_(float x) {
    float t = fast_ex2(-2.8853901f * x);
    return fmaf(2.0f, fast_rcp(1.0f + t), -1.0f);
}
// fast (feedforward disc only; proven rel_err ~2.7e-6)
__device__ __forceinline__ float tanh_a(float x) {
    float y; asm("tanh.approx.f32 %0, %1;" : "=f"(y) : "f"(x)); return y;
}

// dot over N (multiple of 4) smem weights (16B-aligned rows) x register vector
template <int N>
__device__ __forceinline__ float dotN_acc(const float* __restrict__ w,
                                          const float* __restrict__ v, float acc) {
#pragma unroll
    for (int k = 0; k < N; k += 4) {
        float4 wv = *reinterpret_cast<const float4*>(w + k);
        acc = fmaf(v[k + 0], wv.x, acc);
        acc = fmaf(v[k + 1], wv.y, acc);
        acc = fmaf(v[k + 2], wv.z, acc);
        acc = fmaf(v[k + 3], wv.w, acc);
    }
    return acc;
}

// ---------------------------------------------------------------------------
// Generator: direction split at BLOCK granularity + gate-row split across a
// THREAD PAIR (even lane: rows 0..7, odd lane: rows 8..15). Both lanes hold a
// full copy of h[16]; per step they exchange the 8 new h values via shfl_xor.
// All register arrays compile-time indexed; single smem weight array with a
// lane offset (no runtime-selected bases).
// Blocks [0,nb): fwd. [nb,2nb): bwd. Last block: decoder recurrence.
// ---------------------------------------------------------------------------
__global__ void __launch_bounds__(128)
gen_kernel(const float* __restrict__ values, const int* __restrict__ masks,
           const float* __restrict__ gfU, const float* __restrict__ gfW, const float* __restrict__ gfb,
           const float* __restrict__ gbU, const float* __restrict__ gbW, const float* __restrict__ gbb,
           const float* __restrict__ impW, const float* __restrict__ impB,
           const float* __restrict__ dWih, const float* __restrict__ dWhh,
           const float* __restrict__ db_, const float* __restrict__ dOW, const float* __restrict__ dOB,
           int B)
{
    __shared__ __align__(16) float sU[1024];
    __shared__ __align__(16) float sW[64], sB[64];
    __shared__ __align__(16) float sImpW[16], sInit[32];
    __shared__ __align__(16) float sAux[1024];   // decoder Whh / spare

    const int NT = 128;
    int tid = threadIdx.x;

    // ---- last block: batch-independent decoder recurrence ----
    if (blockIdx.x == gridDim.x - 1) {
        float* sWih = sU;          // 1024
        float* sWhh = sAux;        // 1024
        float* sb   = sW;          // 64
        float* sOW  = sImpW;       // 16
        float* shd  = sInit;       // 16
        float* scd  = sInit + 16;  // 16
        float* sgat = sB;          // 64

        for (int i = tid; i < 1024; i += NT) { sWih[i] = dWih[i]; sWhh[i] = dWhh[i]; }
        if (tid < 64) sb[tid] = db_[tid];
        if (tid < 16) sOW[tid] = dOW[tid];
        __syncthreads();

        if (tid < 16) {
            float si = sb[tid], sg = sb[tid + 32], so = sb[tid + 48];
#pragma unroll
            for (int k = 0; k < 16; k++) {
                si = fmaf(128.0f, sWih[(tid +  0) * 16 + k], si);
                sg = fmaf(128.0f, sWih[(tid + 32) * 16 + k], sg);
                so = fmaf(128.0f, sWih[(tid + 48) * 16 + k], so);
            }
            float c = sigmoidf_(si) * tanhf_(sg);
            float h = sigmoidf_(so) * tanhf_(c);
            shd[tid] = h; scd[tid] = c;
        }
        __syncthreads();

        for (int s = 0; s < S16; s++) {
            if (tid < 64) {
                float acc = sb[tid];
#pragma unroll
                for (int k = 0; k < 16; k++)
                    acc = fmaf(scd[k], sWih[tid * 16 + k], fmaf(shd[k], sWhh[tid * 16 + k], acc));
                sgat[tid] = acc;
            }
            __syncthreads();
            if (tid < 16) {
                float c = fmaf(sigmoidf_(sgat[tid + 16]), scd[tid],
                               sigmoidf_(sgat[tid]) * tanhf_(sgat[tid + 32]));
                float h = sigmoidf_(sgat[tid + 48]) * tanhf_(c);
                scd[tid] = c; shd[tid] = h;
            }
            __syncthreads();
            if (tid == 0) {
                float acc = dOB[0];
#pragma unroll
                for (int k = 0; k < 16; k++) acc = fmaf(shd[k], sOW[k], acc);
                g_dec_recon[s] = acc;
            }
            __syncthreads();
        }
        return;
    }

    // ---- direction for this whole block (uniform) ----
    int nb = (gridDim.x - 1) >> 1;
    int dirb = (blockIdx.x >= nb) ? 1 : 0;
    const float* Ug = dirb ? gbU : gfU;
    const float* Wg = dirb ? gbW : gfW;
    const float* Bg = dirb ? gbb : gfb;
    float x0 = dirb ? -128.0f : 128.0f;

    for (int i = tid; i < 1024; i += NT) sU[i] = Ug[i];
    for (int i = tid; i < 64; i += NT) { sW[i] = Wg[i]; sB[i] = Bg[i]; }
    if (tid < 16) sImpW[tid] = impW[tid];
    __syncthreads();

    // ---- block-local init (x = x0, h = c = 0), 16 threads -> sInit ----
    if (tid < 16) {
        float gi = fmaf(x0, sW[tid],      sB[tid]);
        float gg = fmaf(x0, sW[tid + 32], sB[tid + 32]);
        float go = fmaf(x0, sW[tid + 48], sB[tid + 48]);
        float c = sigmoidf_(gi) * tanhf_(gg);
        sInit[16 + tid] = c;
        sInit[tid] = sigmoidf_(go) * tanhf_(c);
    }
    __syncthreads();

    // ---- thread pair: 2 threads per row, split gate rows ----
    int pairIdx = tid >> 1;         // row within block (0..63)
    int half    = tid & 1;          // 0: rows 0..7, 1: rows 8..15
    int jbase   = half << 3;        // 0 or 8
    int b = (blockIdx.x - (dirb ? nb : 0)) * 64 + pairIdx;
    if (b >= B) return;             // B % 64 == 0: whole warps exit together
    float impb = __ldg(impB);

    const float* vrow = values + (size_t)b * S16;
    const int*   mrow = masks  + (size_t)b * S16;

    float h[16], c[8];
#pragma unroll
    for (int k = 0; k < 16; k++) h[k] = sInit[k];
#pragma unroll
    for (int k = 0; k < 8; k++)  c[k] = sInit[16 + jbase + k];

#pragma unroll 1
    for (int t = 0; t < S16; t++) {
        float xt = __ldg(vrow + t);
        float mt = (float)__ldg(mrow + t);
        float d = dotN_acc<16>(sImpW, h, impb);
        float cc = fmaf(mt, d - xt, xt);

        float hn[8];
#pragma unroll
        for (int jj = 0; jj < 8; jj++) {
            int j = jbase + jj;
            float gi = dotN_acc<16>(sU + (j +  0) * 16, h, fmaf(cc, sW[j +  0], sB[j +  0]));
            float gf = dotN_acc<16>(sU + (j + 16) * 16, h, fmaf(cc, sW[j + 16], sB[j + 16]));
            float gg = dotN_acc<16>(sU + (j + 32) * 16, h, fmaf(cc, sW[j + 32], sB[j + 32]));
            float go = dotN_acc<16>(sU + (j + 48) * 16, h, fmaf(cc, sW[j + 48], sB[j + 48]));
            float cn = fmaf(sigmoidf_(gf), c[jj], sigmoidf_(gi) * tanhf_(gg));
            c[jj] = cn;
            hn[jj] = sigmoidf_(go) * tanhf_(cn);
        }
        // exchange the 8 new h values with the partner lane (no dynamic reg idx)
#pragma unroll
        for (int k = 0; k < 8; k++) {
            float other = __shfl_xor_sync(0xffffffffu, hn[k], 1);
            float lo = half ? other : hn[k];
            float hi = half ? hn[k] : other;
            h[k]     = lo;
            h[8 + k] = hi;
        }
    }

    // even lane stores the full final h for this direction
    if (half == 0) {
        float4* d4 = reinterpret_cast<float4*>(&g_h[dirb][(size_t)b * 16]);
#pragma unroll
        for (int i = 0; i < 4; i++)
            d4[i] = make_float4(h[4 * i], h[4 * i + 1], h[4 * i + 2], h[4 * i + 3]);
    }
}

// ---------------------------------------------------------------------------
// Discriminator + combine epilogue (VERBATIM R10). Thread (b,s): hs = hf+hb,
// imputed (bit-identical fma), latent row s, then the disc net.
// ---------------------------------------------------------------------------
__global__ void __launch_bounds__(256, 3)
disc_kernel(const float* __restrict__ values, const int* __restrict__ masks,
            const float* __restrict__ fcW, const float* __restrict__ fcB,
            const float* __restrict__ W0, const float* __restrict__ b0,
            const float* __restrict__ W1, const float* __restrict__ b1,
            const float* __restrict__ W2, const float* __restrict__ b2,
            const float* __restrict__ W3, const float* __restrict__ b3,
            const float* __restrict__ W4, const float* __restrict__ b4,
            const float* __restrict__ dow, const float* __restrict__ dob,
            float* out, int BS)
{
    __shared__ __align__(16) float sW1[1536], sW4[1536];   // [48][32], [96][16]
    __shared__ __align__(16) float sW2[384],  sW3[384];    // [24][16], [48][8]
    __shared__ __align__(16) float sW0[96], sB0[96], sB4[96];
    __shared__ __align__(16) float sB1[48], sB3[48], sB2[24], sDow[32];
    __shared__ __align__(16) float sFcWT[256], sFcB[16];   // fcW transposed [k][l]
    __shared__ float sRec[16];
    __shared__ float sDob;

    const int NT = 256;
    int tid = threadIdx.x;

    for (int i = tid; i < 1536; i += NT) {
        { int j = i >> 5, k = i & 31; int t = j >> 4;
          int row = j + ((t > 0) ? 16 : 0);
          float sc = (t == 1) ? 1.0f : 0.5f;
          sW1[i] = sc * W1[row * 32 + k]; }
        { int j = i >> 4, k = i & 15; int t = j >> 5;
          int row = j + ((t > 0) ? 32 : 0);
          float sc = (t == 1) ? 1.0f : 0.5f;
          sW4[i] = sc * W4[row * 16 + k]; }
    }
    for (int i = tid; i < 384; i += NT) {
        { int j = i >> 4, k = i & 15; int t = j >> 3;
          int row = j + ((t > 0) ? 8 : 0);
          float sc = (t == 1) ? 1.0f : 0.5f;
          sW2[i] = sc * W2[row * 16 + k]; }
        { int j = i >> 3, k = i & 7; int t = j >> 4;
          int row = j + ((t > 0) ? 16 : 0);
          float sc = (t == 1) ? 1.0f : 0.5f;
          sW3[i] = sc * W3[row * 8 + k]; }
    }
    for (int i = tid; i < 96; i += NT) {
        int t = i >> 5; int row = i + ((t > 0) ? 32 : 0);
        float sc = (t == 1) ? 1.0f : 0.5f;
        sW0[i] = sc * W0[row];
        sB0[i] = sc * b0[row];
        sB4[i] = sc * b4[row];
    }
    for (int i = tid; i < 256; i += NT) {
        int k = i >> 4, l = i & 15;
        sFcWT[i] = fcW[l * 16 + k];      // transpose: [k][l]
    }
    if (tid < 48) {
        int t = tid >> 4; int row = tid + ((t > 0) ? 16 : 0);
        float sc = (t == 1) ? 1.0f : 0.5f;
        sB1[tid] = sc * b1[row];
        sB3[tid] = sc * b3[row];
    }
    if (tid < 24) {
        int t = tid >> 3; int row = tid + ((t > 0) ? 8 : 0);
        float sc = (t == 1) ? 1.0f : 0.5f;
        sB2[tid] = sc * b2[row];
    }
    if (tid < 32) sDow[tid] = dow[tid];
    if (tid < 16) { sRec[tid] = g_dec_recon[tid]; sFcB[tid] = fcB[tid]; }
    if (tid == 0) sDob = dob[0];
    __syncthreads();

    int idx = blockIdx.x * NT + tid;
    if (idx >= BS) return;

    int b = idx >> 4, s = idx & 15;

    // ---- combine epilogue: hs = hf + hb ----
    float hs[16];
    {
        const float4* hf4 = reinterpret_cast<const float4*>(&g_h[0][(size_t)b * 16]);
        const float4* hb4 = reinterpret_cast<const float4*>(&g_h[1][(size_t)b * 16]);
#pragma unroll
        for (int i = 0; i < 4; i++) {
            float4 f = __ldg(hf4 + i), g = __ldg(hb4 + i);
            hs[4 * i + 0] = f.x + g.x;
            hs[4 * i + 1] = f.y + g.y;
            hs[4 * i + 2] = f.z + g.z;
            hs[4 * i + 3] = f.w + g.w;
        }
    }

    float xt = __ldg(values + idx);
    float mt = (float)__ldg(masks + idx);
    float a = fmaf(mt, xt - hs[s], hs[s]);        // imputed (bit-identical)
    out[idx] = a;

    // latent row s = dot(fcW[s], hs) + fcB[s]
    {
        float lat = sFcB[s];
#pragma unroll
        for (int k = 0; k < 16; k++) lat = fmaf(hs[k], sFcWT[k * 16 + s], lat);
        out[2 * (size_t)BS + idx] = lat;
    }

#define UNIT(hi, gg, ho, dst)                                     \
    {                                                             \
        float si = fmaf(0.5f, tanh_a(hi), 0.5f);                  \
        float so = fmaf(0.5f, tanh_a(ho), 0.5f);                  \
        float cc = si * tanh_a(gg);                               \
        dst = so * tanh_a(cc);                                    \
    }

    float v0[32];
#pragma unroll
    for (int j = 0; j < 32; j++) {
        float hi = fmaf(a, sW0[j],      sB0[j]);
        float gg = fmaf(a, sW0[32 + j], sB0[32 + j]);
        float ho = fmaf(a, sW0[64 + j], sB0[64 + j]);
        UNIT(hi, gg, ho, v0[j]);
    }
    float v1[16];
#pragma unroll
    for (int j = 0; j < 16; j++) {
        float hi = dotN_acc<32>(sW1 + j * 32,        v0, sB1[j]);
        float gg = dotN_acc<32>(sW1 + (16 + j) * 32, v0, sB1[16 + j]);
        float ho = dotN_acc<32>(sW1 + (32 + j) * 32, v0, sB1[32 + j]);
        UNIT(hi, gg, ho, v1[j]);
    }
    float v2[8];
#pragma unroll
    for (int j = 0; j < 8; j++) {
        float hi = dotN_acc<16>(sW2 + j * 16,        v1, sB2[j]);
        float gg = dotN_acc<16>(sW2 + (8 + j) * 16,  v1, sB2[8 + j]);
        float ho = dotN_acc<16>(sW2 + (16 + j) * 16, v1, sB2[16 + j]);
        UNIT(hi, gg, ho, v2[j]);
    }
    float v3[16];
#pragma unroll
    for (int j = 0; j < 16; j++) {
        float hi = dotN_acc<8>(sW3 + j * 8,        v2, sB3[j]);
        float gg = dotN_acc<8>(sW3 + (16 + j) * 8, v2, sB3[16 + j]);
        float ho = dotN_acc<8>(sW3 + (32 + j) * 8, v2, sB3[32 + j]);
        UNIT(hi, gg, ho, v3[j]);
    }
    float r = sDob;
#pragma unroll
    for (int j = 0; j < 32; j++) {
        float hi = dotN_acc<16>(sW4 + j * 16,        v3, sB4[j]);
        float gg = dotN_acc<16>(sW4 + (32 + j) * 16, v3, sB4[32 + j]);
        float ho = dotN_acc<16>(sW4 + (64 + j) * 16, v3, sB4[64 + j]);
        float v4;
        UNIT(hi, gg, ho, v4);
        r = fmaf(v4, sDow[j], r);
    }
#undef UNIT

    out[(size_t)BS + idx] = r;
    out[3 * (size_t)BS + idx] = sRec[s];
}

// ---------------------------------------------------------------------------
extern "C" void kernel_launch(void* const* d_in, const int* in_sizes, int n_in,
                              void* d_out, int out_size)
{
    const float* values = (const float*)d_in[0];
    const int*   masks  = (const int*)  d_in[1];
    const float* gfW = (const float*)d_in[2];
    const float* gfU = (const float*)d_in[3];
    const float* gfb = (const float*)d_in[4];
    const float* gbW = (const float*)d_in[5];
    const float* gbU = (const float*)d_in[6];
    const float* gbb = (const float*)d_in[7];
    const float* impW = (const float*)d_in[8];
    const float* impB = (const float*)d_in[9];
    const float* fcW  = (const float*)d_in[10];
    const float* fcB  = (const float*)d_in[11];
    const float* dWih = (const float*)d_in[12];
    const float* dWhh = (const float*)d_in[13];
    const float* db_  = (const float*)d_in[14];
    const float* dOW  = (const float*)d_in[15];
    const float* dOB  = (const float*)d_in[16];
    const float* dow  = (const float*)d_in[17];
    const float* dob  = (const float*)d_in[18];
    const float* W0 = (const float*)d_in[19]; const float* b0 = (const float*)d_in[20];
    const float* W1 = (const float*)d_in[21]; const float* b1 = (const float*)d_in[22];
    const float* W2 = (const float*)d_in[23]; const float* b2 = (const float*)d_in[24];
    const float* W3 = (const float*)d_in[25]; const float* b3 = (const float*)d_in[26];
    const float* W4 = (const float*)d_in[27]; const float* b4 = (const float*)d_in[28];

    float* out = (float*)d_out;
    int B  = in_sizes[0] / 16;     // 32768
    int BS = B * 16;               // 524288
    int NB = B / 64;               // 512 blocks per direction (64 rows/block)

    gen_kernel<<<2 * NB + 1, 128>>>(values, masks, gfU, gfW, gfb, gbU, gbW, gbb,
                                    impW, impB, dWih, dWhh, db_, dOW, dOB, B);
    disc_kernel<<<(BS + 255) / 256, 256>>>(values, masks, fcW, fcB,
                                           W0, b0, W1, b1, W2, b2, W3, b3, W4, b4,
                                           dow, dob, out, BS);
}

// round 12
// speedup vs baseline: 1.1538x; 1.1538x over previous
#include <cuda_runtime.h>
#include <cuda_bf16.h>
#include <cstdint>

typedef unsigned long long u64;

// out layout (fp32): [0,BS) imputed | [BS,2BS) disc | [2BS,3BS) latent | [3BS,4BS) recon
// BS = B*16

#define S16 16

__device__ float g_dec_recon[16];        // batch-independent decoder output
__device__ float g_h[2][32768 * 16];     // per-direction final hidden states

// ---- activations ----------------------------------------------------------
__device__ __forceinline__ float fast_ex2(float x) {
    float y; asm("ex2.approx.f32 %0, %1;" : "=f"(y) : "f"(x)); return y;
}
__device__ __forceinline__ float fast_rcp(float x) {
    float y; asm("rcp.approx.f32 %0, %1;" : "=f"(y) : "f"(x)); return y;
}
__device__ __forceinline__ float sigmoidf_(float x) {
    return fast_rcp(1.0f + fast_ex2(-1.4426950408889634f * x));
}
__device__ __forceinline__ float tanhf_(float x) {
    float t = fast_ex2(-2.8853901f * x);
    return fmaf(2.0f, fast_rcp(1.0f + t), -1.0f);
}
// fast (feedforward disc only; proven rel_err ~2.7e-6)
__device__ __forceinline__ float tanh_a(float x) {
    float y; asm("tanh.approx.f32 %0, %1;" : "=f"(y) : "f"(x)); return y;
}

// ---- packed f32x2 helpers (disc only) --------------------------------------
__device__ __forceinline__ u64 pk2f(float lo, float hi) {
    u64 r; unsigned a = __float_as_uint(lo), b = __float_as_uint(hi);
    asm("mov.b64 %0, {%1, %2};" : "=l"(r) : "r"(a), "r"(b));
    return r;
}
__device__ __forceinline__ u64 pkdup(float x) { return pk2f(x, x); }
__device__ __forceinline__ void upk(u64 v, float& lo, float& hi) {
    unsigned a, b;
    asm("mov.b64 {%0, %1}, %2;" : "=r"(a), "=r"(b) : "l"(v));
    lo = __uint_as_float(a); hi = __uint_as_float(b);
}
__device__ __forceinline__ u64 f2fma(u64 a, u64 b, u64 c) {
    u64 d;
    asm("fma.rn.f32x2 %0, %1, %2, %3;" : "=l"(d) : "l"(a), "l"(b), "l"(c));
    return d;
}

// packed dot: v packed activations, w dup-packed weights (u64 rows, 16B aligned)
template <int N>
__device__ __forceinline__ u64 dotP(const u64* __restrict__ w,
                                    const u64* __restrict__ v, u64 acc) {
#pragma unroll
    for (int k = 0; k < N; k += 2) {
        ulonglong2 wv = *reinterpret_cast<const ulonglong2*>(w + k);
        acc = f2fma(v[k], wv.x, acc);
        acc = f2fma(v[k + 1], wv.y, acc);
    }
    return acc;
}

// disc unit for a sample pair: identical scalar math per lane (rel_err preserved)
__device__ __forceinline__ u64 unit_pair(u64 hi, u64 gg, u64 ho) {
    float h0, h1, g0, g1, o0, o1;
    upk(hi, h0, h1); upk(gg, g0, g1); upk(ho, o0, o1);
    float si0 = fmaf(0.5f, tanh_a(h0), 0.5f), si1 = fmaf(0.5f, tanh_a(h1), 0.5f);
    float so0 = fmaf(0.5f, tanh_a(o0), 0.5f), so1 = fmaf(0.5f, tanh_a(o1), 0.5f);
    float cc0 = si0 * tanh_a(g0), cc1 = si1 * tanh_a(g1);
    return pk2f(so0 * tanh_a(cc0), so1 * tanh_a(cc1));
}

// scalar dot over N (multiple of 4) smem weights x register vector (gen)
template <int N>
__device__ __forceinline__ float dotN_acc(const float* __restrict__ w,
                                          const float* __restrict__ v, float acc) {
#pragma unroll
    for (int k = 0; k < N; k += 4) {
        float4 wv = *reinterpret_cast<const float4*>(w + k);
        acc = fmaf(v[k + 0], wv.x, acc);
        acc = fmaf(v[k + 1], wv.y, acc);
        acc = fmaf(v[k + 2], wv.z, acc);
        acc = fmaf(v[k + 3], wv.w, acc);
    }
    return acc;
}

// one LSTM cell step, H=16, scalar input cc. h,c live in registers.
__device__ __forceinline__ void lstm_step16(float h[16], float c[16], float cc,
                                            const float* __restrict__ U,
                                            const float* __restrict__ wih,
                                            const float* __restrict__ bias)
{
    float hn[16];
#pragma unroll
    for (int j = 0; j < 16; j++) {
        float gi = dotN_acc<16>(U + (j +  0) * 16, h, fmaf(cc, wih[j +  0], bias[j +  0]));
        float gf = dotN_acc<16>(U + (j + 16) * 16, h, fmaf(cc, wih[j + 16], bias[j + 16]));
        float gg = dotN_acc<16>(U + (j + 32) * 16, h, fmaf(cc, wih[j + 32], bias[j + 32]));
        float go = dotN_acc<16>(U + (j + 48) * 16, h, fmaf(cc, wih[j + 48], bias[j + 48]));
        float cn = fmaf(sigmoidf_(gf), c[j], sigmoidf_(gi) * tanhf_(gg));
        c[j] = cn;
        hn[j] = sigmoidf_(go) * tanhf_(cn);
    }
#pragma unroll
    for (int j = 0; j < 16; j++) h[j] = hn[j];
}

// ---------------------------------------------------------------------------
// Generator (VERBATIM R10): direction split at BLOCK granularity; one thread
// per row; last block runs the batch-independent decoder recurrence.
// ---------------------------------------------------------------------------
__global__ void __launch_bounds__(128)
gen_kernel(const float* __restrict__ values, const int* __restrict__ masks,
           const float* __restrict__ gfU, const float* __restrict__ gfW, const float* __restrict__ gfb,
           const float* __restrict__ gbU, const float* __restrict__ gbW, const float* __restrict__ gbb,
           const float* __restrict__ impW, const float* __restrict__ impB,
           const float* __restrict__ dWih, const float* __restrict__ dWhh,
           const float* __restrict__ db_, const float* __restrict__ dOW, const float* __restrict__ dOB,
           int B)
{
    __shared__ __align__(16) float sU[1024];
    __shared__ __align__(16) float sW[64], sB[64];
    __shared__ __align__(16) float sImpW[16], sInit[32];
    __shared__ __align__(16) float sAux[1024];

    const int NT = 128;
    int tid = threadIdx.x;

    if (blockIdx.x == gridDim.x - 1) {
        float* sWih = sU;
        float* sWhh = sAux;
        float* sb   = sW;
        float* sOW  = sImpW;
        float* shd  = sInit;
        float* scd  = sInit + 16;
        float* sgat = sB;

        for (int i = tid; i < 1024; i += NT) { sWih[i] = dWih[i]; sWhh[i] = dWhh[i]; }
        if (tid < 64) sb[tid] = db_[tid];
        if (tid < 16) sOW[tid] = dOW[tid];
        __syncthreads();

        if (tid < 16) {
            float si = sb[tid], sg = sb[tid + 32], so = sb[tid + 48];
#pragma unroll
            for (int k = 0; k < 16; k++) {
                si = fmaf(128.0f, sWih[(tid +  0) * 16 + k], si);
                sg = fmaf(128.0f, sWih[(tid + 32) * 16 + k], sg);
                so = fmaf(128.0f, sWih[(tid + 48) * 16 + k], so);
            }
            float c = sigmoidf_(si) * tanhf_(sg);
            float h = sigmoidf_(so) * tanhf_(c);
            shd[tid] = h; scd[tid] = c;
        }
        __syncthreads();

        for (int s = 0; s < S16; s++) {
            if (tid < 64) {
                float acc = sb[tid];
#pragma unroll
                for (int k = 0; k < 16; k++)
                    acc = fmaf(scd[k], sWih[tid * 16 + k], fmaf(shd[k], sWhh[tid * 16 + k], acc));
                sgat[tid] = acc;
            }
            __syncthreads();
            if (tid < 16) {
                float c = fmaf(sigmoidf_(sgat[tid + 16]), scd[tid],
                               sigmoidf_(sgat[tid]) * tanhf_(sgat[tid + 32]));
                float h = sigmoidf_(sgat[tid + 48]) * tanhf_(c);
                scd[tid] = c; shd[tid] = h;
            }
            __syncthreads();
            if (tid == 0) {
                float acc = dOB[0];
#pragma unroll
                for (int k = 0; k < 16; k++) acc = fmaf(shd[k], sOW[k], acc);
                g_dec_recon[s] = acc;
            }
            __syncthreads();
        }
        return;
    }

    int nb = (gridDim.x - 1) >> 1;
    int dirb = (blockIdx.x >= nb) ? 1 : 0;
    const float* Ug = dirb ? gbU : gfU;
    const float* Wg = dirb ? gbW : gfW;
    const float* Bg = dirb ? gbb : gfb;
    float x0 = dirb ? -128.0f : 128.0f;

    for (int i = tid; i < 1024; i += NT) sU[i] = Ug[i];
    for (int i = tid; i < 64; i += NT) { sW[i] = Wg[i]; sB[i] = Bg[i]; }
    if (tid < 16) sImpW[tid] = impW[tid];
    __syncthreads();

    if (tid < 16) {
        float gi = fmaf(x0, sW[tid],      sB[tid]);
        float gg = fmaf(x0, sW[tid + 32], sB[tid + 32]);
        float go = fmaf(x0, sW[tid + 48], sB[tid + 48]);
        float c = sigmoidf_(gi) * tanhf_(gg);
        sInit[16 + tid] = c;
        sInit[tid] = sigmoidf_(go) * tanhf_(c);
    }
    __syncthreads();

    int b = (blockIdx.x - (dirb ? nb : 0)) * NT + tid;
    if (b >= B) return;
    float impb = __ldg(impB);

    const float* vrow = values + (size_t)b * S16;
    const int*   mrow = masks  + (size_t)b * S16;

    float h[16], c[16];
#pragma unroll
    for (int k = 0; k < 16; k++) { h[k] = sInit[k]; c[k] = sInit[16 + k]; }

#pragma unroll 1
    for (int t = 0; t < S16; t++) {
        float xt = __ldg(vrow + t);
        float mt = (float)__ldg(mrow + t);
        float d = dotN_acc<16>(sImpW, h, impb);
        float cc = fmaf(mt, d - xt, xt);
        lstm_step16(h, c, cc, sU, sW, sB);
    }

    float* dst = &g_h[dirb][(size_t)b * 16];
    float4* d4 = reinterpret_cast<float4*>(dst);
#pragma unroll
    for (int i = 0; i < 4; i++)
        d4[i] = make_float4(h[4 * i], h[4 * i + 1], h[4 * i + 2], h[4 * i + 3]);
}

// ---------------------------------------------------------------------------
// Discriminator: SAMPLE-PAIR f32x2. Thread handles (b, s) and (b, s+1).
// Weights dup-packed (w,w) as u64 in smem; activations packed per unit in
// the activation epilogue (no broadcast movs in dot loops); only one packed
// activation array live at a time. Per-lane math identical to R10 (rel_err
// preserved). Combine/latent prologue amortized over the pair.
// ---------------------------------------------------------------------------
__global__ void __launch_bounds__(256, 2)
disc_kernel(const float* __restrict__ values, const int* __restrict__ masks,
            const float* __restrict__ fcW, const float* __restrict__ fcB,
            const float* __restrict__ W0, const float* __restrict__ b0,
            const float* __restrict__ W1, const float* __restrict__ b1,
            const float* __restrict__ W2, const float* __restrict__ b2,
            const float* __restrict__ W3, const float* __restrict__ b3,
            const float* __restrict__ W4, const float* __restrict__ b4,
            const float* __restrict__ dow, const float* __restrict__ dob,
            float* out, int BS)
{
    __shared__ __align__(16) u64 sW1d[1536], sW4d[1536];   // dup-packed
    __shared__ __align__(16) u64 sW2d[384],  sW3d[384];
    __shared__ __align__(16) u64 sW0d[96], sB0d[96], sB4d[96];
    __shared__ __align__(16) u64 sB1d[48], sB3d[48], sB2d[24], sDowd[32];
    __shared__ __align__(16) float sFcWT[256], sFcB[16];   // fcW transposed [k][l]
    __shared__ float sRec[16];
    __shared__ float sDob;

    const int NT = 256;
    int tid = threadIdx.x;

    // staging identical index math to R10, values pre-halved for i/o gates,
    // stored duplicated in both f32x2 lanes.
    for (int i = tid; i < 1536; i += NT) {
        { int j = i >> 5, k = i & 31; int t = j >> 4;
          int row = j + ((t > 0) ? 16 : 0);
          float sc = (t == 1) ? 1.0f : 0.5f;
          sW1d[i] = pkdup(sc * W1[row * 32 + k]); }
        { int j = i >> 4, k = i & 15; int t = j >> 5;
          int row = j + ((t > 0) ? 32 : 0);
          float sc = (t == 1) ? 1.0f : 0.5f;
          sW4d[i] = pkdup(sc * W4[row * 16 + k]); }
    }
    for (int i = tid; i < 384; i += NT) {
        { int j = i >> 4, k = i & 15; int t = j >> 3;
          int row = j + ((t > 0) ? 8 : 0);
          float sc = (t == 1) ? 1.0f : 0.5f;
          sW2d[i] = pkdup(sc * W2[row * 16 + k]); }
        { int j = i >> 3, k = i & 7; int t = j >> 4;
          int row = j + ((t > 0) ? 16 : 0);
          float sc = (t == 1) ? 1.0f : 0.5f;
          sW3d[i] = pkdup(sc * W3[row * 8 + k]); }
    }
    for (int i = tid; i < 96; i += NT) {
        int t = i >> 5; int row = i + ((t > 0) ? 32 : 0);
        float sc = (t == 1) ? 1.0f : 0.5f;
        sW0d[i] = pkdup(sc * W0[row]);
        sB0d[i] = pkdup(sc * b0[row]);
        sB4d[i] = pkdup(sc * b4[row]);
    }
    for (int i = tid; i < 256; i += NT) {
        int k = i >> 4, l = i & 15;
        sFcWT[i] = fcW[l * 16 + k];
    }
    if (tid < 48) {
        int t = tid >> 4; int row = tid + ((t > 0) ? 16 : 0);
        float sc = (t == 1) ? 1.0f : 0.5f;
        sB1d[tid] = pkdup(sc * b1[row]);
        sB3d[tid] = pkdup(sc * b3[row]);
    }
    if (tid < 24) {
        int t = tid >> 3; int row = tid + ((t > 0) ? 8 : 0);
        float sc = (t == 1) ? 1.0f : 0.5f;
        sB2d[tid] = pkdup(sc * b2[row]);
    }
    if (tid < 32) sDowd[tid] = pkdup(dow[tid]);
    if (tid < 16) { sRec[tid] = g_dec_recon[tid]; sFcB[tid] = fcB[tid]; }
    if (tid == 0) sDob = dob[0];
    __syncthreads();

    int g = blockIdx.x * NT + tid;   // sample-pair index
    int idx0 = 2 * g;
    if (idx0 >= BS) return;

    int b = idx0 >> 4, s0 = idx0 & 15;   // s0 even; pair = (b,s0),(b,s0+1)

    // ---- combine: hs = hf + hb (once per pair) ----
    float hs[16];
    {
        const float4* hf4 = reinterpret_cast<const float4*>(&g_h[0][(size_t)b * 16]);
        const float4* hb4 = reinterpret_cast<const float4*>(&g_h[1][(size_t)b * 16]);
#pragma unroll
        for (int i = 0; i < 4; i++) {
            float4 f = __ldg(hf4 + i), gq = __ldg(hb4 + i);
            hs[4 * i + 0] = f.x + gq.x;
            hs[4 * i + 1] = f.y + gq.y;
            hs[4 * i + 2] = f.z + gq.z;
            hs[4 * i + 3] = f.w + gq.w;
        }
    }

    float2 xv = *reinterpret_cast<const float2*>(values + idx0);
    int2   mv = *reinterpret_cast<const int2*>(masks + idx0);
    float a0 = fmaf((float)mv.x, xv.x - hs[s0],     hs[s0]);
    float a1 = fmaf((float)mv.y, xv.y - hs[s0 + 1], hs[s0 + 1]);
    *reinterpret_cast<float2*>(out + idx0) = make_float2(a0, a1);

    // latent rows s0, s0+1
    {
        float lat0 = sFcB[s0], lat1 = sFcB[s0 + 1];
#pragma unroll
        for (int k = 0; k < 16; k++) {
            float hk = hs[k];
            lat0 = fmaf(hk, sFcWT[k * 16 + s0],     lat0);
            lat1 = fmaf(hk, sFcWT[k * 16 + s0 + 1], lat1);
        }
        *reinterpret_cast<float2*>(out + 2 * (size_t)BS + idx0) = make_float2(lat0, lat1);
    }
    // recon (batch-independent)
    *reinterpret_cast<float2*>(out + 3 * (size_t)BS + idx0) =
        make_float2(sRec[s0], sRec[s0 + 1]);

    // ---- packed disc net ----
    u64 ap = pk2f(a0, a1);

    u64 v0[32];
#pragma unroll
    for (int j = 0; j < 32; j++) {
        v0[j] = unit_pair(f2fma(ap, sW0d[j],      sB0d[j]),
                          f2fma(ap, sW0d[32 + j], sB0d[32 + j]),
                          f2fma(ap, sW0d[64 + j], sB0d[64 + j]));
    }
    u64 v1[16];
#pragma unroll
    for (int j = 0; j < 16; j++) {
        v1[j] = unit_pair(dotP<32>(sW1d + j * 32,        v0, sB1d[j]),
                          dotP<32>(sW1d + (16 + j) * 32, v0, sB1d[16 + j]),
                          dotP<32>(sW1d + (32 + j) * 32, v0, sB1d[32 + j]));
    }
    u64 v2[8];
#pragma unroll
    for (int j = 0; j < 8; j++) {
        v2[j] = unit_pair(dotP<16>(sW2d + j * 16,        v1, sB2d[j]),
                          dotP<16>(sW2d + (8 + j) * 16,  v1, sB2d[8 + j]),
                          dotP<16>(sW2d + (16 + j) * 16, v1, sB2d[16 + j]));
    }
    u64 v3[16];
#pragma unroll
    for (int j = 0; j < 16; j++) {
        v3[j] = unit_pair(dotP<8>(sW3d + j * 8,        v2, sB3d[j]),
                          dotP<8>(sW3d + (16 + j) * 8, v2, sB3d[16 + j]),
                          dotP<8>(sW3d + (32 + j) * 8, v2, sB3d[32 + j]));
    }
    float dob0 = sDob;
    u64 acc = pk2f(dob0, dob0);
#pragma unroll
    for (int j = 0; j < 32; j++) {
        u64 v4 = unit_pair(dotP<16>(sW4d + j * 16,        v3, sB4d[j]),
                           dotP<16>(sW4d + (32 + j) * 16, v3, sB4d[32 + j]),
                           dotP<16>(sW4d + (64 + j) * 16, v3, sB4d[64 + j]));
        acc = f2fma(v4, sDowd[j], acc);
    }
    float r0, r1; upk(acc, r0, r1);
    *reinterpret_cast<float2*>(out + (size_t)BS + idx0) = make_float2(r0, r1);
}

// ---------------------------------------------------------------------------
extern "C" void kernel_launch(void* const* d_in, const int* in_sizes, int n_in,
                              void* d_out, int out_size)
{
    const float* values = (const float*)d_in[0];
    const int*   masks  = (const int*)  d_in[1];
    const float* gfW = (const float*)d_in[2];
    const float* gfU = (const float*)d_in[3];
    const float* gfb = (const float*)d_in[4];
    const float* gbW = (const float*)d_in[5];
    const float* gbU = (const float*)d_in[6];
    const float* gbb = (const float*)d_in[7];
    const float* impW = (const float*)d_in[8];
    const float* impB = (const float*)d_in[9];
    const float* fcW  = (const float*)d_in[10];
    const float* fcB  = (const float*)d_in[11];
    const float* dWih = (const float*)d_in[12];
    const float* dWhh = (const float*)d_in[13];
    const float* db_  = (const float*)d_in[14];
    const float* dOW  = (const float*)d_in[15];
    const float* dOB  = (const float*)d_in[16];
    const float* dow  = (const float*)d_in[17];
    const float* dob  = (const float*)d_in[18];
    const float* W0 = (const float*)d_in[19]; const float* b0 = (const float*)d_in[20];
    const float* W1 = (const float*)d_in[21]; const float* b1 = (const float*)d_in[22];
    const float* W2 = (const float*)d_in[23]; const float* b2 = (const float*)d_in[24];
    const float* W3 = (const float*)d_in[25]; const float* b3 = (const float*)d_in[26];
    const float* W4 = (const float*)d_in[27]; const float* b4 = (const float*)d_in[28];

    float* out = (float*)d_out;
    int B  = in_sizes[0] / 16;     // 32768
    int BS = B * 16;               // 524288
    int NB = (B + 127) / 128;      // 256 blocks per direction

    gen_kernel<<<2 * NB + 1, 128>>>(values, masks, gfU, gfW, gfb, gbU, gbW, gbb,
                                    impW, impB, dWih, dWhh, db_, dOW, dOB, B);
    disc_kernel<<<(BS / 2 + 255) / 256, 256>>>(values, masks, fcW, fcB,
                                               W0, b0, W1, b1, W2, b2, W3, b3, W4, b4,
                                               dow, dob, out, BS);
}

// round 13
// speedup vs baseline: 1.2043x; 1.0438x over previous
#include <cuda_runtime.h>
#include <cuda_bf16.h>
#include <cstdint>

typedef unsigned long long u64;

// out layout (fp32): [0,BS) imputed | [BS,2BS) disc | [2BS,3BS) latent | [3BS,4BS) recon
// BS = B*16

#define S16 16

__device__ float g_dec_recon[16];        // batch-independent decoder output
__device__ float g_h[2][32768 * 16];     // per-direction final hidden states

// ---- activations ----------------------------------------------------------
__device__ __forceinline__ float fast_ex2(float x) {
    float y; asm("ex2.approx.f32 %0, %1;" : "=f"(y) : "f"(x)); return y;
}
__device__ __forceinline__ float fast_rcp(float x) {
    float y; asm("rcp.approx.f32 %0, %1;" : "=f"(y) : "f"(x)); return y;
}
__device__ __forceinline__ float sigmoidf_(float x) {
    return fast_rcp(1.0f + fast_ex2(-1.4426950408889634f * x));
}
__device__ __forceinline__ float tanhf_(float x) {
    float t = fast_ex2(-2.8853901f * x);
    return fmaf(2.0f, fast_rcp(1.0f + t), -1.0f);
}
// fast single-MUFU tanh (proven rel_err ~2.7e-6 through 5 chained disc layers)
__device__ __forceinline__ float tanh_a(float x) {
    float y; asm("tanh.approx.f32 %0, %1;" : "=f"(y) : "f"(x)); return y;
}

// ---- packed f32x2 helpers (disc only) --------------------------------------
__device__ __forceinline__ u64 pk2f(float lo, float hi) {
    u64 r; unsigned a = __float_as_uint(lo), b = __float_as_uint(hi);
    asm("mov.b64 %0, {%1, %2};" : "=l"(r) : "r"(a), "r"(b));
    return r;
}
__device__ __forceinline__ u64 pkdup(float x) { return pk2f(x, x); }
__device__ __forceinline__ void upk(u64 v, float& lo, float& hi) {
    unsigned a, b;
    asm("mov.b64 {%0, %1}, %2;" : "=r"(a), "=r"(b) : "l"(v));
    lo = __uint_as_float(a); hi = __uint_as_float(b);
}
__device__ __forceinline__ u64 f2fma(u64 a, u64 b, u64 c) {
    u64 d;
    asm("fma.rn.f32x2 %0, %1, %2, %3;" : "=l"(d) : "l"(a), "l"(b), "l"(c));
    return d;
}

// packed dot: v packed activations, w dup-packed weights (u64 rows, 16B aligned)
template <int N>
__device__ __forceinline__ u64 dotP(const u64* __restrict__ w,
                                    const u64* __restrict__ v, u64 acc) {
#pragma unroll
    for (int k = 0; k < N; k += 2) {
        ulonglong2 wv = *reinterpret_cast<const ulonglong2*>(w + k);
        acc = f2fma(v[k], wv.x, acc);
        acc = f2fma(v[k + 1], wv.y, acc);
    }
    return acc;
}

// disc unit for a sample pair: identical scalar math per lane
__device__ __forceinline__ u64 unit_pair(u64 hi, u64 gg, u64 ho) {
    float h0, h1, g0, g1, o0, o1;
    upk(hi, h0, h1); upk(gg, g0, g1); upk(ho, o0, o1);
    float si0 = fmaf(0.5f, tanh_a(h0), 0.5f), si1 = fmaf(0.5f, tanh_a(h1), 0.5f);
    float so0 = fmaf(0.5f, tanh_a(o0), 0.5f), so1 = fmaf(0.5f, tanh_a(o1), 0.5f);
    float cc0 = si0 * tanh_a(g0), cc1 = si1 * tanh_a(g1);
    return pk2f(so0 * tanh_a(cc0), so1 * tanh_a(cc1));
}

// scalar dot over N (multiple of 4) smem weights x register vector (gen)
template <int N>
__device__ __forceinline__ float dotN_acc(const float* __restrict__ w,
                                          const float* __restrict__ v, float acc) {
#pragma unroll
    for (int k = 0; k < N; k += 4) {
        float4 wv = *reinterpret_cast<const float4*>(w + k);
        acc = fmaf(v[k + 0], wv.x, acc);
        acc = fmaf(v[k + 1], wv.y, acc);
        acc = fmaf(v[k + 2], wv.z, acc);
        acc = fmaf(v[k + 3], wv.w, acc);
    }
    return acc;
}

// one LSTM cell step, H=16, scalar input cc. h,c live in registers.
// EXPECTS i/f/o gate rows of U, wih, bias PRE-HALVED (g rows full scale):
// sigmoid(x) = 0.5*tanh(x/2)+0.5 with the /2 folded into the weights (exact).
// 5 MUFU per row (was 10 with the ex2/rcp forms).
__device__ __forceinline__ void lstm_step16(float h[16], float c[16], float cc,
                                            const float* __restrict__ U,
                                            const float* __restrict__ wih,
                                            const float* __restrict__ bias)
{
    float hn[16];
#pragma unroll
    for (int j = 0; j < 16; j++) {
        float gi = dotN_acc<16>(U + (j +  0) * 16, h, fmaf(cc, wih[j +  0], bias[j +  0]));
        float gf = dotN_acc<16>(U + (j + 16) * 16, h, fmaf(cc, wih[j + 16], bias[j + 16]));
        float gg = dotN_acc<16>(U + (j + 32) * 16, h, fmaf(cc, wih[j + 32], bias[j + 32]));
        float go = dotN_acc<16>(U + (j + 48) * 16, h, fmaf(cc, wih[j + 48], bias[j + 48]));
        float si = fmaf(0.5f, tanh_a(gi), 0.5f);
        float sf = fmaf(0.5f, tanh_a(gf), 0.5f);
        float so = fmaf(0.5f, tanh_a(go), 0.5f);
        float cn = fmaf(sf, c[j], si * tanh_a(gg));
        c[j] = cn;
        hn[j] = so * tanh_a(cn);
    }
#pragma unroll
    for (int j = 0; j < 16; j++) h[j] = hn[j];
}

// ---------------------------------------------------------------------------
// Generator: direction split at BLOCK granularity; one thread per row;
// last block runs the batch-independent decoder recurrence (accurate path).
// CHANGED vs R12: gen staging pre-halves i/f/o gate rows; lstm_step16 uses
// single-MUFU tanh.approx activations (gen MUFU per row 10 -> 5).
// ---------------------------------------------------------------------------
__global__ void __launch_bounds__(128)
gen_kernel(const float* __restrict__ values, const int* __restrict__ masks,
           const float* __restrict__ gfU, const float* __restrict__ gfW, const float* __restrict__ gfb,
           const float* __restrict__ gbU, const float* __restrict__ gbW, const float* __restrict__ gbb,
           const float* __restrict__ impW, const float* __restrict__ impB,
           const float* __restrict__ dWih, const float* __restrict__ dWhh,
           const float* __restrict__ db_, const float* __restrict__ dOW, const float* __restrict__ dOB,
           int B)
{
    __shared__ __align__(16) float sU[1024];
    __shared__ __align__(16) float sW[64], sB[64];
    __shared__ __align__(16) float sImpW[16], sInit[32];
    __shared__ __align__(16) float sAux[1024];

    const int NT = 128;
    int tid = threadIdx.x;

    if (blockIdx.x == gridDim.x - 1) {
        float* sWih = sU;
        float* sWhh = sAux;
        float* sb   = sW;
        float* sOW  = sImpW;
        float* shd  = sInit;
        float* scd  = sInit + 16;
        float* sgat = sB;

        for (int i = tid; i < 1024; i += NT) { sWih[i] = dWih[i]; sWhh[i] = dWhh[i]; }
        if (tid < 64) sb[tid] = db_[tid];
        if (tid < 16) sOW[tid] = dOW[tid];
        __syncthreads();

        if (tid < 16) {
            float si = sb[tid], sg = sb[tid + 32], so = sb[tid + 48];
#pragma unroll
            for (int k = 0; k < 16; k++) {
                si = fmaf(128.0f, sWih[(tid +  0) * 16 + k], si);
                sg = fmaf(128.0f, sWih[(tid + 32) * 16 + k], sg);
                so = fmaf(128.0f, sWih[(tid + 48) * 16 + k], so);
            }
            float c = sigmoidf_(si) * tanhf_(sg);
            float h = sigmoidf_(so) * tanhf_(c);
            shd[tid] = h; scd[tid] = c;
        }
        __syncthreads();

        for (int s = 0; s < S16; s++) {
            if (tid < 64) {
                float acc = sb[tid];
#pragma unroll
                for (int k = 0; k < 16; k++)
                    acc = fmaf(scd[k], sWih[tid * 16 + k], fmaf(shd[k], sWhh[tid * 16 + k], acc));
                sgat[tid] = acc;
            }
            __syncthreads();
            if (tid < 16) {
                float c = fmaf(sigmoidf_(sgat[tid + 16]), scd[tid],
                               sigmoidf_(sgat[tid]) * tanhf_(sgat[tid + 32]));
                float h = sigmoidf_(sgat[tid + 48]) * tanhf_(c);
                scd[tid] = c; shd[tid] = h;
            }
            __syncthreads();
            if (tid == 0) {
                float acc = dOB[0];
#pragma unroll
                for (int k = 0; k < 16; k++) acc = fmaf(shd[k], sOW[k], acc);
                g_dec_recon[s] = acc;
            }
            __syncthreads();
        }
        return;
    }

    int nb = (gridDim.x - 1) >> 1;
    int dirb = (blockIdx.x >= nb) ? 1 : 0;
    const float* Ug = dirb ? gbU : gfU;
    const float* Wg = dirb ? gbW : gfW;
    const float* Bg = dirb ? gbb : gfb;
    float x0 = dirb ? -128.0f : 128.0f;

    // stage with i/f/o rows pre-halved (rows [0,32) and [48,64)); g rows full.
    for (int i = tid; i < 1024; i += NT) {
        int row = i >> 4;
        float sc = (row >= 32 && row < 48) ? 1.0f : 0.5f;
        sU[i] = sc * Ug[i];
    }
    for (int i = tid; i < 64; i += NT) {
        float sc = (i >= 32 && i < 48) ? 1.0f : 0.5f;
        sW[i] = sc * Wg[i];
        sB[i] = sc * Bg[i];
    }
    if (tid < 16) sImpW[tid] = impW[tid];
    __syncthreads();

    // block-local init (x = x0, h = c = 0); i/o rows are pre-halved
    if (tid < 16) {
        float gi = fmaf(x0, sW[tid],      sB[tid]);        // halved
        float gg = fmaf(x0, sW[tid + 32], sB[tid + 32]);   // full
        float go = fmaf(x0, sW[tid + 48], sB[tid + 48]);   // halved
        float c = fmaf(0.5f, tanh_a(gi), 0.5f) * tanh_a(gg);
        sInit[16 + tid] = c;
        sInit[tid] = fmaf(0.5f, tanh_a(go), 0.5f) * tanh_a(c);
    }
    __syncthreads();

    int b = (blockIdx.x - (dirb ? nb : 0)) * NT + tid;
    if (b >= B) return;
    float impb = __ldg(impB);

    const float* vrow = values + (size_t)b * S16;
    const int*   mrow = masks  + (size_t)b * S16;

    float h[16], c[16];
#pragma unroll
    for (int k = 0; k < 16; k++) { h[k] = sInit[k]; c[k] = sInit[16 + k]; }

#pragma unroll 1
    for (int t = 0; t < S16; t++) {
        float xt = __ldg(vrow + t);
        float mt = (float)__ldg(mrow + t);
        float d = dotN_acc<16>(sImpW, h, impb);
        float cc = fmaf(mt, d - xt, xt);
        lstm_step16(h, c, cc, sU, sW, sB);
    }

    float* dst = &g_h[dirb][(size_t)b * 16];
    float4* d4 = reinterpret_cast<float4*>(dst);
#pragma unroll
    for (int i = 0; i < 4; i++)
        d4[i] = make_float4(h[4 * i], h[4 * i + 1], h[4 * i + 2], h[4 * i + 3]);
}

// ---------------------------------------------------------------------------
// Discriminator (VERBATIM R12): SAMPLE-PAIR f32x2; combine/latent amortized.
// ---------------------------------------------------------------------------
__global__ void __launch_bounds__(256, 2)
disc_kernel(const float* __restrict__ values, const int* __restrict__ masks,
            const float* __restrict__ fcW, const float* __restrict__ fcB,
            const float* __restrict__ W0, const float* __restrict__ b0,
            const float* __restrict__ W1, const float* __restrict__ b1,
            const float* __restrict__ W2, const float* __restrict__ b2,
            const float* __restrict__ W3, const float* __restrict__ b3,
            const float* __restrict__ W4, const float* __restrict__ b4,
            const float* __restrict__ dow, const float* __restrict__ dob,
            float* out, int BS)
{
    __shared__ __align__(16) u64 sW1d[1536], sW4d[1536];
    __shared__ __align__(16) u64 sW2d[384],  sW3d[384];
    __shared__ __align__(16) u64 sW0d[96], sB0d[96], sB4d[96];
    __shared__ __align__(16) u64 sB1d[48], sB3d[48], sB2d[24], sDowd[32];
    __shared__ __align__(16) float sFcWT[256], sFcB[16];
    __shared__ float sRec[16];
    __shared__ float sDob;

    const int NT = 256;
    int tid = threadIdx.x;

    for (int i = tid; i < 1536; i += NT) {
        { int j = i >> 5, k = i & 31; int t = j >> 4;
          int row = j + ((t > 0) ? 16 : 0);
          float sc = (t == 1) ? 1.0f : 0.5f;
          sW1d[i] = pkdup(sc * W1[row * 32 + k]); }
        { int j = i >> 4, k = i & 15; int t = j >> 5;
          int row = j + ((t > 0) ? 32 : 0);
          float sc = (t == 1) ? 1.0f : 0.5f;
          sW4d[i] = pkdup(sc * W4[row * 16 + k]); }
    }
    for (int i = tid; i < 384; i += NT) {
        { int j = i >> 4, k = i & 15; int t = j >> 3;
          int row = j + ((t > 0) ? 8 : 0);
          float sc = (t == 1) ? 1.0f : 0.5f;
          sW2d[i] = pkdup(sc * W2[row * 16 + k]); }
        { int j = i >> 3, k = i & 7; int t = j >> 4;
          int row = j + ((t > 0) ? 16 : 0);
          float sc = (t == 1) ? 1.0f : 0.5f;
          sW3d[i] = pkdup(sc * W3[row * 8 + k]); }
    }
    for (int i = tid; i < 96; i += NT) {
        int t = i >> 5; int row = i + ((t > 0) ? 32 : 0);
        float sc = (t == 1) ? 1.0f : 0.5f;
        sW0d[i] = pkdup(sc * W0[row]);
        sB0d[i] = pkdup(sc * b0[row]);
        sB4d[i] = pkdup(sc * b4[row]);
    }
    for (int i = tid; i < 256; i += NT) {
        int k = i >> 4, l = i & 15;
        sFcWT[i] = fcW[l * 16 + k];
    }
    if (tid < 48) {
        int t = tid >> 4; int row = tid + ((t > 0) ? 16 : 0);
        float sc = (t == 1) ? 1.0f : 0.5f;
        sB1d[tid] = pkdup(sc * b1[row]);
        sB3d[tid] = pkdup(sc * b3[row]);
    }
    if (tid < 24) {
        int t = tid >> 3; int row = tid + ((t > 0) ? 8 : 0);
        float sc = (t == 1) ? 1.0f : 0.5f;
        sB2d[tid] = pkdup(sc * b2[row]);
    }
    if (tid < 32) sDowd[tid] = pkdup(dow[tid]);
    if (tid < 16) { sRec[tid] = g_dec_recon[tid]; sFcB[tid] = fcB[tid]; }
    if (tid == 0) sDob = dob[0];
    __syncthreads();

    int g = blockIdx.x * NT + tid;
    int idx0 = 2 * g;
    if (idx0 >= BS) return;

    int b = idx0 >> 4, s0 = idx0 & 15;

    float hs[16];
    {
        const float4* hf4 = reinterpret_cast<const float4*>(&g_h[0][(size_t)b * 16]);
        const float4* hb4 = reinterpret_cast<const float4*>(&g_h[1][(size_t)b * 16]);
#pragma unroll
        for (int i = 0; i < 4; i++) {
            float4 f = __ldg(hf4 + i), gq = __ldg(hb4 + i);
            hs[4 * i + 0] = f.x + gq.x;
            hs[4 * i + 1] = f.y + gq.y;
            hs[4 * i + 2] = f.z + gq.z;
            hs[4 * i + 3] = f.w + gq.w;
        }
    }

    float2 xv = *reinterpret_cast<const float2*>(values + idx0);
    int2   mv = *reinterpret_cast<const int2*>(masks + idx0);
    float a0 = fmaf((float)mv.x, xv.x - hs[s0],     hs[s0]);
    float a1 = fmaf((float)mv.y, xv.y - hs[s0 + 1], hs[s0 + 1]);
    *reinterpret_cast<float2*>(out + idx0) = make_float2(a0, a1);

    {
        float lat0 = sFcB[s0], lat1 = sFcB[s0 + 1];
#pragma unroll
        for (int k = 0; k < 16; k++) {
            float hk = hs[k];
            lat0 = fmaf(hk, sFcWT[k * 16 + s0],     lat0);
            lat1 = fmaf(hk, sFcWT[k * 16 + s0 + 1], lat1);
        }
        *reinterpret_cast<float2*>(out + 2 * (size_t)BS + idx0) = make_float2(lat0, lat1);
    }
    *reinterpret_cast<float2*>(out + 3 * (size_t)BS + idx0) =
        make_float2(sRec[s0], sRec[s0 + 1]);

    u64 ap = pk2f(a0, a1);

    u64 v0[32];
#pragma unroll
    for (int j = 0; j < 32; j++) {
        v0[j] = unit_pair(f2fma(ap, sW0d[j],      sB0d[j]),
                          f2fma(ap, sW0d[32 + j], sB0d[32 + j]),
                          f2fma(ap, sW0d[64 + j], sB0d[64 + j]));
    }
    u64 v1[16];
#pragma unroll
    for (int j = 0; j < 16; j++) {
        v1[j] = unit_pair(dotP<32>(sW1d + j * 32,        v0, sB1d[j]),
                          dotP<32>(sW1d + (16 + j) * 32, v0, sB1d[16 + j]),
                          dotP<32>(sW1d + (32 + j) * 32, v0, sB1d[32 + j]));
    }
    u64 v2[8];
#pragma unroll
    for (int j = 0; j < 8; j++) {
        v2[j] = unit_pair(dotP<16>(sW2d + j * 16,        v1, sB2d[j]),
                          dotP<16>(sW2d + (8 + j) * 16,  v1, sB2d[8 + j]),
                          dotP<16>(sW2d + (16 + j) * 16, v1, sB2d[16 + j]));
    }
    u64 v3[16];
#pragma unroll
    for (int j = 0; j < 16; j++) {
        v3[j] = unit_pair(dotP<8>(sW3d + j * 8,        v2, sB3d[j]),
                          dotP<8>(sW3d + (16 + j) * 8, v2, sB3d[16 + j]),
                          dotP<8>(sW3d + (32 + j) * 8, v2, sB3d[32 + j]));
    }
    float dob0 = sDob;
    u64 acc = pk2f(dob0, dob0);
#pragma unroll
    for (int j = 0; j < 32; j++) {
        u64 v4 = unit_pair(dotP<16>(sW4d + j * 16,        v3, sB4d[j]),
                           dotP<16>(sW4d + (32 + j) * 16, v3, sB4d[32 + j]),
                           dotP<16>(sW4d + (64 + j) * 16, v3, sB4d[64 + j]));
        acc = f2fma(v4, sDowd[j], acc);
    }
    float r0, r1; upk(acc, r0, r1);
    *reinterpret_cast<float2*>(out + (size_t)BS + idx0) = make_float2(r0, r1);
}

// ---------------------------------------------------------------------------
extern "C" void kernel_launch(void* const* d_in, const int* in_sizes, int n_in,
                              void* d_out, int out_size)
{
    const float* values = (const float*)d_in[0];
    const int*   masks  = (const int*)  d_in[1];
    const float* gfW = (const float*)d_in[2];
    const float* gfU = (const float*)d_in[3];
    const float* gfb = (const float*)d_in[4];
    const float* gbW = (const float*)d_in[5];
    const float* gbU = (const float*)d_in[6];
    const float* gbb = (const float*)d_in[7];
    const float* impW = (const float*)d_in[8];
    const float* impB = (const float*)d_in[9];
    const float* fcW  = (const float*)d_in[10];
    const float* fcB  = (const float*)d_in[11];
    const float* dWih = (const float*)d_in[12];
    const float* dWhh = (const float*)d_in[13];
    const float* db_  = (const float*)d_in[14];
    const float* dOW  = (const float*)d_in[15];
    const float* dOB  = (const float*)d_in[16];
    const float* dow  = (const float*)d_in[17];
    const float* dob  = (const float*)d_in[18];
    const float* W0 = (const float*)d_in[19]; const float* b0 = (const float*)d_in[20];
    const float* W1 = (const float*)d_in[21]; const float* b1 = (const float*)d_in[22];
    const float* W2 = (const float*)d_in[23]; const float* b2 = (const float*)d_in[24];
    const float* W3 = (const float*)d_in[25]; const float* b3 = (const float*)d_in[26];
    const float* W4 = (const float*)d_in[27]; const float* b4 = (const float*)d_in[28];

    float* out = (float*)d_out;
    int B  = in_sizes[0] / 16;     // 32768
    int BS = B * 16;               // 524288
    int NB = (B + 127) / 128;      // 256 blocks per direction

    gen_kernel<<<2 * NB + 1, 128>>>(values, masks, gfU, gfW, gfb, gbU, gbW, gbb,
                                    impW, impB, dWih, dWhh, db_, dOW, dOB, B);
    disc_kernel<<<(BS / 2 + 255) / 256, 256>>>(values, masks, fcW, fcB,
                                               W0, b0, W1, b1, W2, b2, W3, b3, W4, b4,
                                               dow, dob, out, BS);
}

// round 14
// speedup vs baseline: 1.2803x; 1.0631x over previous
#include <cuda_runtime.h>
#include <cuda_bf16.h>
#include <cstdint>

// out layout (fp32): [0,BS) imputed | [BS,2BS) disc | [2BS,3BS) latent | [3BS,4BS) recon
// BS = B*16

#define S16 16

__device__ float g_dec_recon[16];        // batch-independent decoder output
__device__ float g_h[2][32768 * 16];     // per-direction final hidden states

// ---- activations ----------------------------------------------------------
__device__ __forceinline__ float fast_ex2(float x) {
    float y; asm("ex2.approx.f32 %0, %1;" : "=f"(y) : "f"(x)); return y;
}
__device__ __forceinline__ float fast_rcp(float x) {
    float y; asm("rcp.approx.f32 %0, %1;" : "=f"(y) : "f"(x)); return y;
}
__device__ __forceinline__ float sigmoidf_(float x) {
    return fast_rcp(1.0f + fast_ex2(-1.4426950408889634f * x));
}
__device__ __forceinline__ float tanhf_(float x) {
    float t = fast_ex2(-2.8853901f * x);
    return fmaf(2.0f, fast_rcp(1.0f + t), -1.0f);
}
// fast single-MUFU tanh
__device__ __forceinline__ float tanh_a(float x) {
    float y; asm("tanh.approx.f32 %0, %1;" : "=f"(y) : "f"(x)); return y;
}

// scalar dot over N (multiple of 4) smem weights x register vector
template <int N>
__device__ __forceinline__ float dotN_acc(const float* __restrict__ w,
                                          const float* __restrict__ v, float acc) {
#pragma unroll
    for (int k = 0; k < N; k += 4) {
        float4 wv = *reinterpret_cast<const float4*>(w + k);
        acc = fmaf(v[k + 0], wv.x, acc);
        acc = fmaf(v[k + 1], wv.y, acc);
        acc = fmaf(v[k + 2], wv.z, acc);
        acc = fmaf(v[k + 3], wv.w, acc);
    }
    return acc;
}

// dual-sample dot: ONE float4 weight load feeds both samples (halves L1 wf)
template <int N>
__device__ __forceinline__ void dot2(const float* __restrict__ w,
                                     const float* __restrict__ va,
                                     const float* __restrict__ vb,
                                     float& ra, float& rb) {
#pragma unroll
    for (int k = 0; k < N; k += 4) {
        float4 wv = *reinterpret_cast<const float4*>(w + k);
        ra = fmaf(va[k + 0], wv.x, ra); rb = fmaf(vb[k + 0], wv.x, rb);
        ra = fmaf(va[k + 1], wv.y, ra); rb = fmaf(vb[k + 1], wv.y, rb);
        ra = fmaf(va[k + 2], wv.z, ra); rb = fmaf(vb[k + 2], wv.z, rb);
        ra = fmaf(va[k + 3], wv.w, ra); rb = fmaf(vb[k + 3], wv.w, rb);
    }
}

// one LSTM cell step, H=16, scalar input cc. h,c live in registers.
// EXPECTS i/f/o gate rows of U, wih, bias PRE-HALVED (g rows full scale).
__device__ __forceinline__ void lstm_step16(float h[16], float c[16], float cc,
                                            const float* __restrict__ U,
                                            const float* __restrict__ wih,
                                            const float* __restrict__ bias)
{
    float hn[16];
#pragma unroll
    for (int j = 0; j < 16; j++) {
        float gi = dotN_acc<16>(U + (j +  0) * 16, h, fmaf(cc, wih[j +  0], bias[j +  0]));
        float gf = dotN_acc<16>(U + (j + 16) * 16, h, fmaf(cc, wih[j + 16], bias[j + 16]));
        float gg = dotN_acc<16>(U + (j + 32) * 16, h, fmaf(cc, wih[j + 32], bias[j + 32]));
        float go = dotN_acc<16>(U + (j + 48) * 16, h, fmaf(cc, wih[j + 48], bias[j + 48]));
        float si = fmaf(0.5f, tanh_a(gi), 0.5f);
        float sf = fmaf(0.5f, tanh_a(gf), 0.5f);
        float so = fmaf(0.5f, tanh_a(go), 0.5f);
        float cn = fmaf(sf, c[j], si * tanh_a(gg));
        c[j] = cn;
        hn[j] = so * tanh_a(cn);
    }
#pragma unroll
    for (int j = 0; j < 16; j++) h[j] = hn[j];
}

// ---------------------------------------------------------------------------
// Generator (VERBATIM R13): block-granular direction split, pre-halved i/f/o
// rows + single-MUFU activations; last block runs the decoder recurrence.
// ---------------------------------------------------------------------------
__global__ void __launch_bounds__(128)
gen_kernel(const float* __restrict__ values, const int* __restrict__ masks,
           const float* __restrict__ gfU, const float* __restrict__ gfW, const float* __restrict__ gfb,
           const float* __restrict__ gbU, const float* __restrict__ gbW, const float* __restrict__ gbb,
           const float* __restrict__ impW, const float* __restrict__ impB,
           const float* __restrict__ dWih, const float* __restrict__ dWhh,
           const float* __restrict__ db_, const float* __restrict__ dOW, const float* __restrict__ dOB,
           int B)
{
    __shared__ __align__(16) float sU[1024];
    __shared__ __align__(16) float sW[64], sB[64];
    __shared__ __align__(16) float sImpW[16], sInit[32];
    __shared__ __align__(16) float sAux[1024];

    const int NT = 128;
    int tid = threadIdx.x;

    if (blockIdx.x == gridDim.x - 1) {
        float* sWih = sU;
        float* sWhh = sAux;
        float* sb   = sW;
        float* sOW  = sImpW;
        float* shd  = sInit;
        float* scd  = sInit + 16;
        float* sgat = sB;

        for (int i = tid; i < 1024; i += NT) { sWih[i] = dWih[i]; sWhh[i] = dWhh[i]; }
        if (tid < 64) sb[tid] = db_[tid];
        if (tid < 16) sOW[tid] = dOW[tid];
        __syncthreads();

        if (tid < 16) {
            float si = sb[tid], sg = sb[tid + 32], so = sb[tid + 48];
#pragma unroll
            for (int k = 0; k < 16; k++) {
                si = fmaf(128.0f, sWih[(tid +  0) * 16 + k], si);
                sg = fmaf(128.0f, sWih[(tid + 32) * 16 + k], sg);
                so = fmaf(128.0f, sWih[(tid + 48) * 16 + k], so);
            }
            float c = sigmoidf_(si) * tanhf_(sg);
            float h = sigmoidf_(so) * tanhf_(c);
            shd[tid] = h; scd[tid] = c;
        }
        __syncthreads();

        for (int s = 0; s < S16; s++) {
            if (tid < 64) {
                float acc = sb[tid];
#pragma unroll
                for (int k = 0; k < 16; k++)
                    acc = fmaf(scd[k], sWih[tid * 16 + k], fmaf(shd[k], sWhh[tid * 16 + k], acc));
                sgat[tid] = acc;
            }
            __syncthreads();
            if (tid < 16) {
                float c = fmaf(sigmoidf_(sgat[tid + 16]), scd[tid],
                               sigmoidf_(sgat[tid]) * tanhf_(sgat[tid + 32]));
                float h = sigmoidf_(sgat[tid + 48]) * tanhf_(c);
                scd[tid] = c; shd[tid] = h;
            }
            __syncthreads();
            if (tid == 0) {
                float acc = dOB[0];
#pragma unroll
                for (int k = 0; k < 16; k++) acc = fmaf(shd[k], sOW[k], acc);
                g_dec_recon[s] = acc;
            }
            __syncthreads();
        }
        return;
    }

    int nb = (gridDim.x - 1) >> 1;
    int dirb = (blockIdx.x >= nb) ? 1 : 0;
    const float* Ug = dirb ? gbU : gfU;
    const float* Wg = dirb ? gbW : gfW;
    const float* Bg = dirb ? gbb : gfb;
    float x0 = dirb ? -128.0f : 128.0f;

    for (int i = tid; i < 1024; i += NT) {
        int row = i >> 4;
        float sc = (row >= 32 && row < 48) ? 1.0f : 0.5f;
        sU[i] = sc * Ug[i];
    }
    for (int i = tid; i < 64; i += NT) {
        float sc = (i >= 32 && i < 48) ? 1.0f : 0.5f;
        sW[i] = sc * Wg[i];
        sB[i] = sc * Bg[i];
    }
    if (tid < 16) sImpW[tid] = impW[tid];
    __syncthreads();

    if (tid < 16) {
        float gi = fmaf(x0, sW[tid],      sB[tid]);
        float gg = fmaf(x0, sW[tid + 32], sB[tid + 32]);
        float go = fmaf(x0, sW[tid + 48], sB[tid + 48]);
        float c = fmaf(0.5f, tanh_a(gi), 0.5f) * tanh_a(gg);
        sInit[16 + tid] = c;
        sInit[tid] = fmaf(0.5f, tanh_a(go), 0.5f) * tanh_a(c);
    }
    __syncthreads();

    int b = (blockIdx.x - (dirb ? nb : 0)) * NT + tid;
    if (b >= B) return;
    float impb = __ldg(impB);

    const float* vrow = values + (size_t)b * S16;
    const int*   mrow = masks  + (size_t)b * S16;

    float h[16], c[16];
#pragma unroll
    for (int k = 0; k < 16; k++) { h[k] = sInit[k]; c[k] = sInit[16 + k]; }

#pragma unroll 1
    for (int t = 0; t < S16; t++) {
        float xt = __ldg(vrow + t);
        float mt = (float)__ldg(mrow + t);
        float d = dotN_acc<16>(sImpW, h, impb);
        float cc = fmaf(mt, d - xt, xt);
        lstm_step16(h, c, cc, sU, sW, sB);
    }

    float* dst = &g_h[dirb][(size_t)b * 16];
    float4* d4 = reinterpret_cast<float4*>(dst);
#pragma unroll
    for (int i = 0; i < 4; i++)
        d4[i] = make_float4(h[4 * i], h[4 * i + 1], h[4 * i + 2], h[4 * i + 3]);
}

// ---------------------------------------------------------------------------
// Discriminator: scalar, TWO samples per thread (adjacent (b,s0),(b,s0+1))
// with every float4 weight load shared between both samples (halves L1
// wavefronts per sample — the measured bottleneck). Per-lane math identical
// to the R10 scalar sequence. Combine/latent prologue amortized per pair.
// ---------------------------------------------------------------------------
__global__ void __launch_bounds__(256, 2)
disc_kernel(const float* __restrict__ values, const int* __restrict__ masks,
            const float* __restrict__ fcW, const float* __restrict__ fcB,
            const float* __restrict__ W0, const float* __restrict__ b0,
            const float* __restrict__ W1, const float* __restrict__ b1,
            const float* __restrict__ W2, const float* __restrict__ b2,
            const float* __restrict__ W3, const float* __restrict__ b3,
            const float* __restrict__ W4, const float* __restrict__ b4,
            const float* __restrict__ dow, const float* __restrict__ dob,
            float* out, int BS)
{
    __shared__ __align__(16) float sW1[1536], sW4[1536];   // [48][32], [96][16]
    __shared__ __align__(16) float sW2[384],  sW3[384];    // [24][16], [48][8]
    __shared__ __align__(16) float sW0[96], sB0[96], sB4[96];
    __shared__ __align__(16) float sB1[48], sB3[48], sB2[24], sDow[32];
    __shared__ __align__(16) float sFcWT[256], sFcB[16];
    __shared__ float sRec[16];
    __shared__ float sDob;

    const int NT = 256;
    int tid = threadIdx.x;

    // staging (R10 layout: pre-halved i/o rows; f rows skipped)
    for (int i = tid; i < 1536; i += NT) {
        { int j = i >> 5, k = i & 31; int t = j >> 4;
          int row = j + ((t > 0) ? 16 : 0);
          float sc = (t == 1) ? 1.0f : 0.5f;
          sW1[i] = sc * W1[row * 32 + k]; }
        { int j = i >> 4, k = i & 15; int t = j >> 5;
          int row = j + ((t > 0) ? 32 : 0);
          float sc = (t == 1) ? 1.0f : 0.5f;
          sW4[i] = sc * W4[row * 16 + k]; }
    }
    for (int i = tid; i < 384; i += NT) {
        { int j = i >> 4, k = i & 15; int t = j >> 3;
          int row = j + ((t > 0) ? 8 : 0);
          float sc = (t == 1) ? 1.0f : 0.5f;
          sW2[i] = sc * W2[row * 16 + k]; }
        { int j = i >> 3, k = i & 7; int t = j >> 4;
          int row = j + ((t > 0) ? 16 : 0);
          float sc = (t == 1) ? 1.0f : 0.5f;
          sW3[i] = sc * W3[row * 8 + k]; }
    }
    for (int i = tid; i < 96; i += NT) {
        int t = i >> 5; int row = i + ((t > 0) ? 32 : 0);
        float sc = (t == 1) ? 1.0f : 0.5f;
        sW0[i] = sc * W0[row];
        sB0[i] = sc * b0[row];
        sB4[i] = sc * b4[row];
    }
    for (int i = tid; i < 256; i += NT) {
        int k = i >> 4, l = i & 15;
        sFcWT[i] = fcW[l * 16 + k];
    }
    if (tid < 48) {
        int t = tid >> 4; int row = tid + ((t > 0) ? 16 : 0);
        float sc = (t == 1) ? 1.0f : 0.5f;
        sB1[tid] = sc * b1[row];
        sB3[tid] = sc * b3[row];
    }
    if (tid < 24) {
        int t = tid >> 3; int row = tid + ((t > 0) ? 8 : 0);
        float sc = (t == 1) ? 1.0f : 0.5f;
        sB2[tid] = sc * b2[row];
    }
    if (tid < 32) sDow[tid] = dow[tid];
    if (tid < 16) { sRec[tid] = g_dec_recon[tid]; sFcB[tid] = fcB[tid]; }
    if (tid == 0) sDob = dob[0];
    __syncthreads();

    int g = blockIdx.x * NT + tid;   // sample-pair index
    int idx0 = 2 * g;
    if (idx0 >= BS) return;

    int b = idx0 >> 4, s0 = idx0 & 15;   // s0 even

    // ---- combine: hs = hf + hb (once per pair) ----
    float hs[16];
    {
        const float4* hf4 = reinterpret_cast<const float4*>(&g_h[0][(size_t)b * 16]);
        const float4* hb4 = reinterpret_cast<const float4*>(&g_h[1][(size_t)b * 16]);
#pragma unroll
        for (int i = 0; i < 4; i++) {
            float4 f = __ldg(hf4 + i), gq = __ldg(hb4 + i);
            hs[4 * i + 0] = f.x + gq.x;
            hs[4 * i + 1] = f.y + gq.y;
            hs[4 * i + 2] = f.z + gq.z;
            hs[4 * i + 3] = f.w + gq.w;
        }
    }

    float2 xv = *reinterpret_cast<const float2*>(values + idx0);
    int2   mv = *reinterpret_cast<const int2*>(masks + idx0);
    float a0 = fmaf((float)mv.x, xv.x - hs[s0],     hs[s0]);
    float a1 = fmaf((float)mv.y, xv.y - hs[s0 + 1], hs[s0 + 1]);
    *reinterpret_cast<float2*>(out + idx0) = make_float2(a0, a1);

    {
        float lat0 = sFcB[s0], lat1 = sFcB[s0 + 1];
#pragma unroll
        for (int k = 0; k < 16; k++) {
            float hk = hs[k];
            lat0 = fmaf(hk, sFcWT[k * 16 + s0],     lat0);
            lat1 = fmaf(hk, sFcWT[k * 16 + s0 + 1], lat1);
        }
        *reinterpret_cast<float2*>(out + 2 * (size_t)BS + idx0) = make_float2(lat0, lat1);
    }
    *reinterpret_cast<float2*>(out + 3 * (size_t)BS + idx0) =
        make_float2(sRec[s0], sRec[s0 + 1]);

    // ---- dual-sample disc net (shared weight loads) ----
#define UNIT2(h0, h1, g0, g1, o0, o1, d0, d1)                     \
    {                                                             \
        float si0 = fmaf(0.5f, tanh_a(h0), 0.5f);                 \
        float si1 = fmaf(0.5f, tanh_a(h1), 0.5f);                 \
        float so0 = fmaf(0.5f, tanh_a(o0), 0.5f);                 \
        float so1 = fmaf(0.5f, tanh_a(o1), 0.5f);                 \
        float cc0 = si0 * tanh_a(g0);                             \
        float cc1 = si1 * tanh_a(g1);                             \
        d0 = so0 * tanh_a(cc0);                                   \
        d1 = so1 * tanh_a(cc1);                                   \
    }

    float v0a[32], v0b[32];
#pragma unroll
    for (int j = 0; j < 32; j++) {
        float w0v = sW0[j], w1v = sW0[32 + j], w2v = sW0[64 + j];
        float bi = sB0[j], bg = sB0[32 + j], bo = sB0[64 + j];
        float h0 = fmaf(a0, w0v, bi), h1 = fmaf(a1, w0v, bi);
        float g0v = fmaf(a0, w1v, bg), g1v = fmaf(a1, w1v, bg);
        float o0v = fmaf(a0, w2v, bo), o1v = fmaf(a1, w2v, bo);
        UNIT2(h0, h1, g0v, g1v, o0v, o1v, v0a[j], v0b[j]);
    }
    float v1a[16], v1b[16];
#pragma unroll
    for (int j = 0; j < 16; j++) {
        float h0 = sB1[j],      h1 = sB1[j];
        float g0v = sB1[16 + j], g1v = sB1[16 + j];
        float o0v = sB1[32 + j], o1v = sB1[32 + j];
        dot2<32>(sW1 + j * 32,        v0a, v0b, h0, h1);
        dot2<32>(sW1 + (16 + j) * 32, v0a, v0b, g0v, g1v);
        dot2<32>(sW1 + (32 + j) * 32, v0a, v0b, o0v, o1v);
        UNIT2(h0, h1, g0v, g1v, o0v, o1v, v1a[j], v1b[j]);
    }
    float v2a[8], v2b[8];
#pragma unroll
    for (int j = 0; j < 8; j++) {
        float h0 = sB2[j],      h1 = sB2[j];
        float g0v = sB2[8 + j],  g1v = sB2[8 + j];
        float o0v = sB2[16 + j], o1v = sB2[16 + j];
        dot2<16>(sW2 + j * 16,        v1a, v1b, h0, h1);
        dot2<16>(sW2 + (8 + j) * 16,  v1a, v1b, g0v, g1v);
        dot2<16>(sW2 + (16 + j) * 16, v1a, v1b, o0v, o1v);
        UNIT2(h0, h1, g0v, g1v, o0v, o1v, v2a[j], v2b[j]);
    }
    float v3a[16], v3b[16];
#pragma unroll
    for (int j = 0; j < 16; j++) {
        float h0 = sB3[j],      h1 = sB3[j];
        float g0v = sB3[16 + j], g1v = sB3[16 + j];
        float o0v = sB3[32 + j], o1v = sB3[32 + j];
        dot2<8>(sW3 + j * 8,        v2a, v2b, h0, h1);
        dot2<8>(sW3 + (16 + j) * 8, v2a, v2b, g0v, g1v);
        dot2<8>(sW3 + (32 + j) * 8, v2a, v2b, o0v, o1v);
        UNIT2(h0, h1, g0v, g1v, o0v, o1v, v3a[j], v3b[j]);
    }
    float dob0 = sDob;
    float r0 = dob0, r1 = dob0;
#pragma unroll
    for (int j = 0; j < 32; j++) {
        float h0 = sB4[j],      h1 = sB4[j];
        float g0v = sB4[32 + j], g1v = sB4[32 + j];
        float o0v = sB4[64 + j], o1v = sB4[64 + j];
        dot2<16>(sW4 + j * 16,        v3a, v3b, h0, h1);
        dot2<16>(sW4 + (32 + j) * 16, v3a, v3b, g0v, g1v);
        dot2<16>(sW4 + (64 + j) * 16, v3a, v3b, o0v, o1v);
        float va, vb;
        UNIT2(h0, h1, g0v, g1v, o0v, o1v, va, vb);
        float wj = sDow[j];
        r0 = fmaf(va, wj, r0);
        r1 = fmaf(vb, wj, r1);
    }
#undef UNIT2

    *reinterpret_cast<float2*>(out + (size_t)BS + idx0) = make_float2(r0, r1);
}

// ---------------------------------------------------------------------------
extern "C" void kernel_launch(void* const* d_in, const int* in_sizes, int n_in,
                              void* d_out, int out_size)
{
    const float* values = (const float*)d_in[0];
    const int*   masks  = (const int*)  d_in[1];
    const float* gfW = (const float*)d_in[2];
    const float* gfU = (const float*)d_in[3];
    const float* gfb = (const float*)d_in[4];
    const float* gbW = (const float*)d_in[5];
    const float* gbU = (const float*)d_in[6];
    const float* gbb = (const float*)d_in[7];
    const float* impW = (const float*)d_in[8];
    const float* impB = (const float*)d_in[9];
    const float* fcW  = (const float*)d_in[10];
    const float* fcB  = (const float*)d_in[11];
    const float* dWih = (const float*)d_in[12];
    const float* dWhh = (const float*)d_in[13];
    const float* db_  = (const float*)d_in[14];
    const float* dOW  = (const float*)d_in[15];
    const float* dOB  = (const float*)d_in[16];
    const float* dow  = (const float*)d_in[17];
    const float* dob  = (const float*)d_in[18];
    const float* W0 = (const float*)d_in[19]; const float* b0 = (const float*)d_in[20];
    const float* W1 = (const float*)d_in[21]; const float* b1 = (const float*)d_in[22];
    const float* W2 = (const float*)d_in[23]; const float* b2 = (const float*)d_in[24];
    const float* W3 = (const float*)d_in[25]; const float* b3 = (const float*)d_in[26];
    const float* W4 = (const float*)d_in[27]; const float* b4 = (const float*)d_in[28];

    float* out = (float*)d_out;
    int B  = in_sizes[0] / 16;     // 32768
    int BS = B * 16;               // 524288
    int NB = (B + 127) / 128;      // 256 blocks per direction

    gen_kernel<<<2 * NB + 1, 128>>>(values, masks, gfU, gfW, gfb, gbU, gbW, gbb,
                                    impW, impB, dWih, dWhh, db_, dOW, dOB, B);
    disc_kernel<<<(BS / 2 + 255) / 256, 256>>>(values, masks, fcW, fcB,
                                               W0, b0, W1, b1, W2, b2, W3, b3, W4, b4,
                                               dow, dob, out, BS);
}